// round 2
// baseline (speedup 1.0000x reference)
#include <cuda_runtime.h>
#include <cuda_bf16.h>
#include <cstdint>

#define SPEC   10
#define CCH    64
#define DD     9
#define DOUTV  4
#define NPROJV 32
#define PP1    2
#define PP2    4
#define PP3    4
#define NPROJ_OUT (PP1 + PP2 + PP3)   // 10
#define NQ     45
#define NCUB   165
#define NMONO  (DD + NQ + NCUB)       // 219

// Fused coefficient table: Cf[s][c][mono] -> float4 over u (DOUT=4)
__device__ float4 g_cf[SPEC * CCH * NMONO];
__device__ int    g_off[SPEC + 1];

// ---------------------------------------------------------------------------
// Kernel 0: prefix sum of species counts (S=10, trivial)
// ---------------------------------------------------------------------------
__global__ void prefix_kernel(const int* __restrict__ counts) {
    int acc = 0;
    g_off[0] = 0;
    for (int t = 0; t < SPEC; t++) {
        acc += counts[t];
        g_off[t + 1] = acc;
    }
}

// ---------------------------------------------------------------------------
// Kernel 1: build fused symmetric coefficient table.
// Block = (c, s). Threads 0..9 compute wn[b] = sum_a w[s,a,c]*proj[a,b],
// then thread t (< 219) computes the 4 (u) coefficients of monomial t.
// Monomial order: linear i (9), quad i<=j lex (45), cubic i<=j<=k lex (165).
// ---------------------------------------------------------------------------
__global__ void precompute_kernel(const float* __restrict__ w,
                                  const float* __restrict__ proj,
                                  const float* __restrict__ u1,
                                  const float* __restrict__ u2,
                                  const float* __restrict__ u3) {
    const int c = blockIdx.x;
    const int s = blockIdx.y;
    __shared__ float wn[NPROJ_OUT];

    const int tid = threadIdx.x;
    if (tid < NPROJ_OUT) {
        float acc = 0.f;
        for (int a = 0; a < NPROJV; a++)
            acc += w[(s * NPROJV + a) * CCH + c] * proj[a * NPROJ_OUT + tid];
        wn[tid] = acc;
    }
    __syncthreads();

    const int t = tid;
    if (t >= NMONO) return;

    float val[DOUTV];

    if (t < DD) {
        // linear term i = t:  sum_p u1[u,i,p] * wn[p]
        const int i = t;
        for (int u = 0; u < DOUTV; u++) {
            float a = 0.f;
            for (int p = 0; p < PP1; p++)
                a += u1[(u * DD + i) * PP1 + p] * wn[p];
            val[u] = a;
        }
    } else if (t < DD + NQ) {
        // quadratic monomial x_i x_j (i<=j): symmetrize u2
        int q = t - DD;
        int i = 0;
        while (q >= DD - i) { q -= DD - i; i++; }
        const int j = i + q;
        for (int u = 0; u < DOUTV; u++) {
            float a = 0.f;
            for (int p = 0; p < PP2; p++) {
                float uu = u2[((u * DD + i) * DD + j) * PP2 + p];
                if (j > i)
                    uu += u2[((u * DD + j) * DD + i) * PP2 + p];
                a += uu * wn[PP1 + p];
            }
            val[u] = a;
        }
    } else {
        // cubic monomial x_i x_j x_k (i<=j<=k): symmetrize u3 over distinct perms
        int q = t - DD - NQ;
        int i = 0;
        while (q >= (DD - i) * (DD - i + 1) / 2) { q -= (DD - i) * (DD - i + 1) / 2; i++; }
        int j = i;
        while (q >= DD - j) { q -= DD - j; j++; }
        const int k = j + q;

        const int pi[6] = { i, i, j, j, k, k };
        const int pj[6] = { j, k, i, k, i, j };
        const int pk[6] = { k, j, k, i, j, i };

        for (int u = 0; u < DOUTV; u++) {
            float a = 0.f;
            for (int p = 0; p < PP3; p++) {
                float uu = 0.f;
                for (int t2 = 0; t2 < 6; t2++) {
                    bool dup = false;
                    for (int r = 0; r < t2; r++)
                        if (pi[r] == pi[t2] && pj[r] == pj[t2] && pk[r] == pk[t2])
                            dup = true;
                    if (!dup)
                        uu += u3[(((u * DD + pi[t2]) * DD + pj[t2]) * DD + pk[t2]) * PP3 + p];
                }
                a += uu * wn[PP1 + PP2 + p];
            }
            val[u] = a;
        }
    }

    g_cf[(s * CCH + c) * NMONO + t] = make_float4(val[0], val[1], val[2], val[3]);
}

// ---------------------------------------------------------------------------
// Kernel 2: main contraction. One thread per (n, c).
// Grid: (N/256, C). Warp = 32 consecutive n at fixed c -> coefficient loads
// are warp-uniform (L1 broadcast). out[n,c,:] written as one float4.
// ---------------------------------------------------------------------------
__global__ void __launch_bounds__(256, 1)
main_kernel(const float* __restrict__ x, float4* __restrict__ out, int n_total) {
    const int n = blockIdx.x * 256 + threadIdx.x;
    const int c = blockIdx.y;
    if (n >= n_total) return;

    // species lookup (off is tiny; uniform across warp except boundaries)
    int s = 0;
#pragma unroll
    for (int t = 1; t < SPEC; t++)
        if (n >= g_off[t]) s = t;

    // load x[n, c, 0..8]
    const float* xp = x + ((size_t)n * CCH + c) * DD;
    float xs[DD];
#pragma unroll
    for (int i = 0; i < DD; i++) xs[i] = __ldg(xp + i);

    const float4* cf = g_cf + (size_t)(s * CCH + c) * NMONO;

    float a0 = 0.f, a1 = 0.f, a2 = 0.f, a3 = 0.f;

    // linear terms
#pragma unroll
    for (int i = 0; i < DD; i++) {
        float4 wv = __ldg(cf + i);
        a0 = fmaf(wv.x, xs[i], a0);
        a1 = fmaf(wv.y, xs[i], a1);
        a2 = fmaf(wv.z, xs[i], a2);
        a3 = fmaf(wv.w, xs[i], a3);
    }

    // quadratic + cubic terms (reuse m2 = x_i * x_j)
    int mq = DD;
    int mc = DD + NQ;
#pragma unroll
    for (int i = 0; i < DD; i++) {
#pragma unroll
        for (int j = i; j < DD; j++) {
            const float m2 = xs[i] * xs[j];
            float4 wq = __ldg(cf + mq); mq++;
            a0 = fmaf(wq.x, m2, a0);
            a1 = fmaf(wq.y, m2, a1);
            a2 = fmaf(wq.z, m2, a2);
            a3 = fmaf(wq.w, m2, a3);
#pragma unroll
            for (int k = j; k < DD; k++) {
                const float m3 = m2 * xs[k];
                float4 wc = __ldg(cf + mc); mc++;
                a0 = fmaf(wc.x, m3, a0);
                a1 = fmaf(wc.y, m3, a1);
                a2 = fmaf(wc.z, m3, a2);
                a3 = fmaf(wc.w, m3, a3);
            }
        }
    }

    out[(size_t)n * CCH + c] = make_float4(a0, a1, a2, a3);
}

// ---------------------------------------------------------------------------
extern "C" void kernel_launch(void* const* d_in, const int* in_sizes, int n_in,
                              void* d_out, int out_size) {
    const float* x      = (const float*)d_in[0];   // (N, C, D)
    const float* w      = (const float*)d_in[1];   // (S, NPROJ, C)
    const float* proj   = (const float*)d_in[2];   // (NPROJ, 10)
    const float* u1     = (const float*)d_in[3];   // (DOUT, D, P1)
    const float* u2     = (const float*)d_in[4];   // (DOUT, D, D, P2)
    const float* u3     = (const float*)d_in[5];   // (DOUT, D, D, D, P3)
    const int*   counts = (const int*)d_in[6];     // (S,)

    const int n_total = in_sizes[0] / (CCH * DD);

    prefix_kernel<<<1, 1>>>(counts);
    precompute_kernel<<<dim3(CCH, SPEC), 224>>>(w, proj, u1, u2, u3);
    main_kernel<<<dim3((n_total + 255) / 256, CCH), 256>>>(x, (float4*)d_out, n_total);
}

// round 4
// speedup vs baseline: 1.2086x; 1.2086x over previous
#include <cuda_runtime.h>
#include <cuda_bf16.h>
#include <cstdint>

#define SPEC   10
#define CCH    64
#define DD     9
#define DOUTV  4
#define NPROJV 32
#define PP1    2
#define PP2    4
#define PP3    4
#define NPROJ_OUT (PP1 + PP2 + PP3)   // 10
#define NQ     45
#define NCUB   165
#define NMONO  (DD + NQ + NCUB)       // 219
#define NT     32                      // n-tile per block
#define PITCH  577                     // 577 % 32 == 1 -> conflict-free LDS

// Paired coefficient table: for c-pair (2c,2c+1), per monomial 8 floats:
// [w0(ca),w0(cb), w1(ca),w1(cb), w2(ca),w2(cb), w3(ca),w3(cb)]
// -> two ulonglong2 loads land directly as f32x2 operands.
__device__ float g_cf2[SPEC * (CCH / 2) * NMONO * 8];
__device__ int   g_off[SPEC + 1];

#define FMA2(d, a, b, c) asm("fma.rn.f32x2 %0, %1, %2, %3;" : "=l"(d) : "l"(a), "l"(b), "l"(c))
#define MUL2(d, a, b)    asm("mul.rn.f32x2 %0, %1, %2;"     : "=l"(d) : "l"(a), "l"(b))
#define PACK2(d, lo, hi) asm("mov.b64 %0, {%1, %2};"        : "=l"(d) : "f"(lo), "f"(hi))
#define UNPACK2(lo, hi, s) asm("mov.b64 {%0, %1}, %2;"      : "=f"(lo), "=f"(hi) : "l"(s))

// ---------------------------------------------------------------------------
// Precompute: fused symmetric coefficient table + species prefix sum.
// Block = (c, s), 224 threads. Thread t < 219 computes monomial t's 4 u-coeffs.
// Thread 219 of block (0,0) also writes the species prefix offsets.
// ---------------------------------------------------------------------------
__global__ void precompute_kernel(const float* __restrict__ w,
                                  const float* __restrict__ proj,
                                  const float* __restrict__ u1,
                                  const float* __restrict__ u2,
                                  const float* __restrict__ u3,
                                  const int* __restrict__ counts) {
    const int c = blockIdx.x;
    const int s = blockIdx.y;
    __shared__ float wn[NPROJ_OUT];

    const int tid = threadIdx.x;

    if (tid == 219 && c == 0 && s == 0) {
        int acc = 0;
        g_off[0] = 0;
        for (int q = 0; q < SPEC; q++) { acc += counts[q]; g_off[q + 1] = acc; }
    }

    if (tid < NPROJ_OUT) {
        float acc = 0.f;
        for (int a = 0; a < NPROJV; a++)
            acc += w[(s * NPROJV + a) * CCH + c] * proj[a * NPROJ_OUT + tid];
        wn[tid] = acc;
    }
    __syncthreads();

    const int t = tid;
    if (t >= NMONO) return;

    float val[DOUTV];

    if (t < DD) {
        const int i = t;
        for (int u = 0; u < DOUTV; u++) {
            float a = 0.f;
            for (int p = 0; p < PP1; p++)
                a += u1[(u * DD + i) * PP1 + p] * wn[p];
            val[u] = a;
        }
    } else if (t < DD + NQ) {
        int q = t - DD;
        int i = 0;
        while (q >= DD - i) { q -= DD - i; i++; }
        const int j = i + q;
        for (int u = 0; u < DOUTV; u++) {
            float a = 0.f;
            for (int p = 0; p < PP2; p++) {
                float uu = u2[((u * DD + i) * DD + j) * PP2 + p];
                if (j > i)
                    uu += u2[((u * DD + j) * DD + i) * PP2 + p];
                a += uu * wn[PP1 + p];
            }
            val[u] = a;
        }
    } else {
        int q = t - DD - NQ;
        int i = 0;
        while (q >= (DD - i) * (DD - i + 1) / 2) { q -= (DD - i) * (DD - i + 1) / 2; i++; }
        int j = i;
        while (q >= DD - j) { q -= DD - j; j++; }
        const int k = j + q;

        const int pi[6] = { i, i, j, j, k, k };
        const int pj[6] = { j, k, i, k, i, j };
        const int pk[6] = { k, j, k, i, j, i };

        for (int u = 0; u < DOUTV; u++) {
            float a = 0.f;
            for (int p = 0; p < PP3; p++) {
                float uu = 0.f;
                for (int t2 = 0; t2 < 6; t2++) {
                    bool dup = false;
                    for (int r = 0; r < t2; r++)
                        if (pi[r] == pi[t2] && pj[r] == pj[t2] && pk[r] == pk[t2])
                            dup = true;
                    if (!dup)
                        uu += u3[(((u * DD + pi[t2]) * DD + pj[t2]) * DD + pk[t2]) * PP3 + p];
                }
                a += uu * wn[PP1 + PP2 + p];
            }
            val[u] = a;
        }
    }

    // paired layout write
    const size_t base = ((size_t)(s * (CCH / 2) + (c >> 1)) * NMONO + t) * 8 + (c & 1);
#pragma unroll
    for (int u = 0; u < DOUTV; u++)
        g_cf2[base + 2 * u] = val[u];
}

// ---------------------------------------------------------------------------
// Main: block = 32 n x 64 c, 512 threads; thread = 1 n x 4 c (two c-pairs).
// x staged to smem via coalesced LDG.128; cf loads warp-uniform LDG.128;
// math in packed f32x2 (two c's per instruction).
// ---------------------------------------------------------------------------
__global__ void __launch_bounds__(512)
main_kernel(const float* __restrict__ x, float4* __restrict__ out, int n_total) {
    extern __shared__ float xs_s[];   // [NT][PITCH]

    const int t  = threadIdx.x;
    const int n0 = blockIdx.x * NT;

    // ---- stage x[n0:n0+NT, :, :] (contiguous 32*576 floats) into smem ----
    {
        const int count = min(NT, n_total - n0);
        const int max4 = count * 144;                 // float4s to stage
        const float4* xg = (const float4*)x + (size_t)n0 * 144;
#pragma unroll
        for (int r = 0; r < 9; r++) {                 // 9*512 = 4608 = 32*144
            const int idx4 = t + r * 512;
            if (idx4 < max4) {
                const float4 v = __ldg(xg + idx4);
                const int nr  = idx4 / 144;
                const int off = idx4 - nr * 144;
                float* p = xs_s + nr * PITCH + off * 4;
                p[0] = v.x; p[1] = v.y; p[2] = v.z; p[3] = v.w;
            }
        }
    }
    __syncthreads();

    const int n_l = t & 31;
    const int n   = n0 + n_l;
    if (n >= n_total) return;
    const int c_base = (t >> 5) * 4;   // warp-uniform

    int s = 0;
#pragma unroll
    for (int q = 1; q < SPEC; q++)
        if (n >= g_off[q]) s = q;

    const float* xrow = xs_s + n_l * PITCH;

#pragma unroll
    for (int cc = 0; cc < 2; cc++) {
        const int c = c_base + cc * 2;               // even; pair (c, c+1)
        const ulonglong2* cf = (const ulonglong2*)g_cf2
                             + (size_t)(s * (CCH / 2) + (c >> 1)) * (NMONO * 2);

        // packed x: xp[d] = (x[c][d], x[c+1][d])
        unsigned long long xp[DD];
#pragma unroll
        for (int d = 0; d < DD; d++) {
            const float xa = xrow[c * 9 + d];
            const float xb = xrow[c * 9 + 9 + d];
            PACK2(xp[d], xa, xb);
        }

        unsigned long long a0 = 0ull, a1 = 0ull, a2 = 0ull, a3 = 0ull;

        // linear terms
#pragma unroll
        for (int i = 0; i < DD; i++) {
            const ulonglong2 e0 = __ldg(cf + 2 * i);
            const ulonglong2 e1 = __ldg(cf + 2 * i + 1);
            FMA2(a0, e0.x, xp[i], a0);
            FMA2(a1, e0.y, xp[i], a1);
            FMA2(a2, e1.x, xp[i], a2);
            FMA2(a3, e1.y, xp[i], a3);
        }

        // quadratic + cubic
        int mq = DD;
        int mc = DD + NQ;
#pragma unroll
        for (int i = 0; i < DD; i++) {
#pragma unroll
            for (int j = i; j < DD; j++) {
                unsigned long long m2;
                MUL2(m2, xp[i], xp[j]);
                {
                    const ulonglong2 e0 = __ldg(cf + 2 * mq);
                    const ulonglong2 e1 = __ldg(cf + 2 * mq + 1);
                    mq++;
                    FMA2(a0, e0.x, m2, a0);
                    FMA2(a1, e0.y, m2, a1);
                    FMA2(a2, e1.x, m2, a2);
                    FMA2(a3, e1.y, m2, a3);
                }
#pragma unroll
                for (int k = j; k < DD; k++) {
                    unsigned long long m3;
                    MUL2(m3, m2, xp[k]);
                    const ulonglong2 e0 = __ldg(cf + 2 * mc);
                    const ulonglong2 e1 = __ldg(cf + 2 * mc + 1);
                    mc++;
                    FMA2(a0, e0.x, m3, a0);
                    FMA2(a1, e0.y, m3, a1);
                    FMA2(a2, e1.x, m3, a2);
                    FMA2(a3, e1.y, m3, a3);
                }
            }
        }

        // unpack: lane-lo = c, lane-hi = c+1
        float l0, h0, l1, h1, l2, h2, l3, h3;
        UNPACK2(l0, h0, a0);
        UNPACK2(l1, h1, a1);
        UNPACK2(l2, h2, a2);
        UNPACK2(l3, h3, a3);
        out[(size_t)n * CCH + c]     = make_float4(l0, l1, l2, l3);
        out[(size_t)n * CCH + c + 1] = make_float4(h0, h1, h2, h3);
    }
}

// ---------------------------------------------------------------------------
extern "C" void kernel_launch(void* const* d_in, const int* in_sizes, int n_in,
                              void* d_out, int out_size) {
    const float* x      = (const float*)d_in[0];   // (N, C, D)
    const float* w      = (const float*)d_in[1];   // (S, NPROJ, C)
    const float* proj   = (const float*)d_in[2];   // (NPROJ, 10)
    const float* u1     = (const float*)d_in[3];   // (DOUT, D, P1)
    const float* u2     = (const float*)d_in[4];   // (DOUT, D, D, P2)
    const float* u3     = (const float*)d_in[5];   // (DOUT, D, D, D, P3)
    const int*   counts = (const int*)d_in[6];     // (S,)

    const int n_total = in_sizes[0] / (CCH * DD);
    const int smem_bytes = NT * PITCH * sizeof(float);   // 73856

    cudaFuncSetAttribute(main_kernel,
                         cudaFuncAttributeMaxDynamicSharedMemorySize, smem_bytes);

    precompute_kernel<<<dim3(CCH, SPEC), 224>>>(w, proj, u1, u2, u3, counts);
    main_kernel<<<(n_total + NT - 1) / NT, 512, smem_bytes>>>(x, (float4*)d_out, n_total);
}

// round 7
// speedup vs baseline: 1.3943x; 1.1536x over previous
#include <cuda_runtime.h>
#include <cuda_bf16.h>
#include <cstdint>

#define SPEC   10
#define CCH    64
#define DD     9
#define DOUTV  4
#define NPROJV 32
#define PP1    2
#define PP2    4
#define PP3    4
#define NPROJ_OUT (PP1 + PP2 + PP3)   // 10
#define NQ     45
#define NCUB   165
#define NMONO  (DD + NQ + NCUB)       // 219

#define NTILE   128     // n per block
#define THREADS 128     // 4 warps; warp w owns c-pair (blockIdx.y*4 + w)
#define NB      4       // n per thread
#define PITCH2  73      // 73 % 32 == 9, coprime -> conflict-free LDS rows

// Paired coefficient table: for c-pair (2c,2c+1), per monomial 8 floats:
// [w0(ca),w0(cb), w1(ca),w1(cb), w2(ca),w2(cb), w3(ca),w3(cb)]
__device__ float g_cf2[SPEC * (CCH / 2) * NMONO * 8];
__device__ int   g_off[SPEC + 1];

#define FMA2(d, a, b, c) asm("fma.rn.f32x2 %0, %1, %2, %3;" : "=l"(d) : "l"(a), "l"(b), "l"(c))
#define MUL2(d, a, b)    asm("mul.rn.f32x2 %0, %1, %2;"     : "=l"(d) : "l"(a), "l"(b))
#define PACK2(d, lo, hi) asm("mov.b64 %0, {%1, %2};"        : "=l"(d) : "f"(lo), "f"(hi))
#define UNPACK2(lo, hi, s) asm("mov.b64 {%0, %1}, %2;"      : "=f"(lo), "=f"(hi) : "l"(s))

// ---------------------------------------------------------------------------
// Precompute: fused symmetric coefficient table + species prefix sum.
// ---------------------------------------------------------------------------
__global__ void precompute_kernel(const float* __restrict__ w,
                                  const float* __restrict__ proj,
                                  const float* __restrict__ u1,
                                  const float* __restrict__ u2,
                                  const float* __restrict__ u3,
                                  const int* __restrict__ counts) {
    const int c = blockIdx.x;
    const int s = blockIdx.y;
    __shared__ float wn[NPROJ_OUT];

    const int tid = threadIdx.x;

    if (tid == 219 && c == 0 && s == 0) {
        int acc = 0;
        g_off[0] = 0;
        for (int q = 0; q < SPEC; q++) { acc += counts[q]; g_off[q + 1] = acc; }
    }

    if (tid < NPROJ_OUT) {
        float acc = 0.f;
        for (int a = 0; a < NPROJV; a++)
            acc += w[(s * NPROJV + a) * CCH + c] * proj[a * NPROJ_OUT + tid];
        wn[tid] = acc;
    }
    __syncthreads();

    const int t = tid;
    if (t >= NMONO) return;

    float val[DOUTV];

    if (t < DD) {
        const int i = t;
        for (int u = 0; u < DOUTV; u++) {
            float a = 0.f;
            for (int p = 0; p < PP1; p++)
                a += u1[(u * DD + i) * PP1 + p] * wn[p];
            val[u] = a;
        }
    } else if (t < DD + NQ) {
        int q = t - DD;
        int i = 0;
        while (q >= DD - i) { q -= DD - i; i++; }
        const int j = i + q;
        for (int u = 0; u < DOUTV; u++) {
            float a = 0.f;
            for (int p = 0; p < PP2; p++) {
                float uu = u2[((u * DD + i) * DD + j) * PP2 + p];
                if (j > i)
                    uu += u2[((u * DD + j) * DD + i) * PP2 + p];
                a += uu * wn[PP1 + p];
            }
            val[u] = a;
        }
    } else {
        int q = t - DD - NQ;
        int i = 0;
        while (q >= (DD - i) * (DD - i + 1) / 2) { q -= (DD - i) * (DD - i + 1) / 2; i++; }
        int j = i;
        while (q >= DD - j) { q -= DD - j; j++; }
        const int k = j + q;

        const int pi[6] = { i, i, j, j, k, k };
        const int pj[6] = { j, k, i, k, i, j };
        const int pk[6] = { k, j, k, i, j, i };

        for (int u = 0; u < DOUTV; u++) {
            float a = 0.f;
            for (int p = 0; p < PP3; p++) {
                float uu = 0.f;
                for (int t2 = 0; t2 < 6; t2++) {
                    bool dup = false;
                    for (int r = 0; r < t2; r++)
                        if (pi[r] == pi[t2] && pj[r] == pj[t2] && pk[r] == pk[t2])
                            dup = true;
                    if (!dup)
                        uu += u3[(((u * DD + pi[t2]) * DD + pj[t2]) * DD + pk[t2]) * PP3 + p];
                }
                a += uu * wn[PP1 + PP2 + p];
            }
            val[u] = a;
        }
    }

    const size_t base = ((size_t)(s * (CCH / 2) + (c >> 1)) * NMONO + t) * 8 + (c & 1);
#pragma unroll
    for (int u = 0; u < DOUTV; u++)
        g_cf2[base + 2 * u] = val[u];
}

// ---------------------------------------------------------------------------
// Monomial sweep over NR n's sharing one coefficient stream.
// Each coefficient broadcast (2x LDG.128) feeds 4*NR FMA2s.
// ---------------------------------------------------------------------------
template<int NR>
__device__ __forceinline__ void sweep(const ulonglong2* __restrict__ cf,
                                      const unsigned long long (&xp)[NR][DD],
                                      unsigned long long (&acc)[NR][DOUTV]) {
    // linear
#pragma unroll
    for (int i = 0; i < DD; i++) {
        const ulonglong2 e0 = __ldg(cf + 2 * i);
        const ulonglong2 e1 = __ldg(cf + 2 * i + 1);
#pragma unroll
        for (int r = 0; r < NR; r++) {
            FMA2(acc[r][0], e0.x, xp[r][i], acc[r][0]);
            FMA2(acc[r][1], e0.y, xp[r][i], acc[r][1]);
            FMA2(acc[r][2], e1.x, xp[r][i], acc[r][2]);
            FMA2(acc[r][3], e1.y, xp[r][i], acc[r][3]);
        }
    }

    int mq = DD;
    int mc = DD + NQ;
#pragma unroll
    for (int i = 0; i < DD; i++) {
#pragma unroll
        for (int j = i; j < DD; j++) {
            unsigned long long m2[NR];
#pragma unroll
            for (int r = 0; r < NR; r++)
                MUL2(m2[r], xp[r][i], xp[r][j]);
            {
                const ulonglong2 e0 = __ldg(cf + 2 * mq);
                const ulonglong2 e1 = __ldg(cf + 2 * mq + 1);
                mq++;
#pragma unroll
                for (int r = 0; r < NR; r++) {
                    FMA2(acc[r][0], e0.x, m2[r], acc[r][0]);
                    FMA2(acc[r][1], e0.y, m2[r], acc[r][1]);
                    FMA2(acc[r][2], e1.x, m2[r], acc[r][2]);
                    FMA2(acc[r][3], e1.y, m2[r], acc[r][3]);
                }
            }
#pragma unroll
            for (int k = j; k < DD; k++) {
                unsigned long long m3[NR];
#pragma unroll
                for (int r = 0; r < NR; r++)
                    MUL2(m3[r], m2[r], xp[r][k]);
                const ulonglong2 e0 = __ldg(cf + 2 * mc);
                const ulonglong2 e1 = __ldg(cf + 2 * mc + 1);
                mc++;
#pragma unroll
                for (int r = 0; r < NR; r++) {
                    FMA2(acc[r][0], e0.x, m3[r], acc[r][0]);
                    FMA2(acc[r][1], e0.y, m3[r], acc[r][1]);
                    FMA2(acc[r][2], e1.x, m3[r], acc[r][2]);
                    FMA2(acc[r][3], e1.y, m3[r], acc[r][3]);
                }
            }
        }
    }
}

__device__ __forceinline__ int species_of(int n) {
    int s = 0;
#pragma unroll
    for (int q = 1; q < SPEC; q++)
        if (n >= g_off[q]) s = q;
    return s;
}

// ---------------------------------------------------------------------------
// Main: block = 128 n x 4 c-pairs (8 channels), 128 threads (4 warps).
// Thread = 4 n x 1 c-pair. Grid = (N/128, 8).
// ---------------------------------------------------------------------------
__global__ void __launch_bounds__(THREADS, 3)
main_kernel(const float* __restrict__ x, float4* __restrict__ out, int n_total) {
    __shared__ float xs[NTILE * PITCH2];   // [128 n][72 floats + pad]

    const int tid = threadIdx.x;
    const int n0  = blockIdx.x * NTILE;
    const int cg  = blockIdx.y;            // channel-group: channels [8cg, 8cg+8)

    // ---- stage x[n0:n0+128, 8cg:8cg+8, :] = 128 rows x 72 contiguous floats
    {
        const float4* xg = (const float4*)x;
#pragma unroll
        for (int it = 0; it < 18; it++) {
            const int idx = tid + it * THREADS;      // 0..2303
            const int row = idx / 18;
            const int col = idx - row * 18;
            if (n0 + row < n_total) {
                const float4 v = __ldg(xg + (size_t)(n0 + row) * 144 + cg * 18 + col);
                float* p = xs + row * PITCH2 + col * 4;
                p[0] = v.x; p[1] = v.y; p[2] = v.z; p[3] = v.w;
            }
        }
    }
    __syncthreads();

    const int warp = tid >> 5;
    const int lane = tid & 31;
    const int cl   = warp * 2;             // local channel (0,2,4,6)
    const int c    = cg * 8 + cl;          // global even channel; pair (c, c+1)
    const int cp   = c >> 1;               // global c-pair index

    // build packed xp and zero accumulators
    unsigned long long xp[NB][DD];
    unsigned long long acc[NB][DOUTV];
#pragma unroll
    for (int r = 0; r < NB; r++) {
        const float* rowp = xs + (lane + 32 * r) * PITCH2 + cl * 9;
#pragma unroll
        for (int d = 0; d < DD; d++)
            PACK2(xp[r][d], rowp[d], rowp[9 + d]);
#pragma unroll
        for (int u = 0; u < DOUTV; u++)
            acc[r][u] = 0ull;
    }

    const int nLast = min(n0 + NTILE - 1, n_total - 1);
    const int sLo = species_of(n0);
    const int sHi = species_of(nLast);

    if (sLo == sHi) {
        // uniform species across tile (always true for equal counts)
        const ulonglong2* cf = (const ulonglong2*)g_cf2
                             + (size_t)(sLo * (CCH / 2) + cp) * (NMONO * 2);
        sweep<NB>(cf, xp, acc);
    } else {
        // species boundary inside tile: per-n sweep (rare / correctness path)
#pragma unroll 1
        for (int r = 0; r < NB; r++) {
            const int n = n0 + lane + 32 * r;
            const int s = species_of(min(n, n_total - 1));
            const ulonglong2* cf = (const ulonglong2*)g_cf2
                                 + (size_t)(s * (CCH / 2) + cp) * (NMONO * 2);
            unsigned long long xp1[1][DD];
            unsigned long long ac1[1][DOUTV];
#pragma unroll
            for (int d = 0; d < DD; d++) xp1[0][d] = xp[r][d];
#pragma unroll
            for (int u = 0; u < DOUTV; u++) ac1[0][u] = 0ull;
            sweep<1>(cf, xp1, ac1);
#pragma unroll
            for (int u = 0; u < DOUTV; u++) acc[r][u] = ac1[0][u];
        }
    }

    // stores
#pragma unroll
    for (int r = 0; r < NB; r++) {
        const int n = n0 + lane + 32 * r;
        if (n >= n_total) continue;
        float l0, h0, l1, h1, l2, h2, l3, h3;
        UNPACK2(l0, h0, acc[r][0]);
        UNPACK2(l1, h1, acc[r][1]);
        UNPACK2(l2, h2, acc[r][2]);
        UNPACK2(l3, h3, acc[r][3]);
        out[(size_t)n * CCH + c]     = make_float4(l0, l1, l2, l3);
        out[(size_t)n * CCH + c + 1] = make_float4(h0, h1, h2, h3);
    }
}

// ---------------------------------------------------------------------------
extern "C" void kernel_launch(void* const* d_in, const int* in_sizes, int n_in,
                              void* d_out, int out_size) {
    const float* x      = (const float*)d_in[0];   // (N, C, D)
    const float* w      = (const float*)d_in[1];   // (S, NPROJ, C)
    const float* proj   = (const float*)d_in[2];   // (NPROJ, 10)
    const float* u1     = (const float*)d_in[3];   // (DOUT, D, P1)
    const float* u2     = (const float*)d_in[4];   // (DOUT, D, D, P2)
    const float* u3     = (const float*)d_in[5];   // (DOUT, D, D, D, P3)
    const int*   counts = (const int*)d_in[6];     // (S,)

    const int n_total = in_sizes[0] / (CCH * DD);

    precompute_kernel<<<dim3(CCH, SPEC), 224>>>(w, proj, u1, u2, u3, counts);
    main_kernel<<<dim3((n_total + NTILE - 1) / NTILE, 8), THREADS>>>(
        x, (float4*)d_out, n_total);
}